// round 7
// baseline (speedup 1.0000x reference)
#include <cuda_runtime.h>
#include <cuda_bf16.h>
#include <cstdint>

// LSTM B=65536, T=7, H=128, fused recurrence via warp-level mma.sync (bf16->f32).
// CTA = 512 thr / 16 warps / 64 rows, TWO independent 8-warp groups (named bars).
// NEW vs R6: x*W_ih + bias folded into the MMA as an augmented-K chunk via
// mma.m16n8k8 with register-synthesized fragments (hi/lo bf16 split keeps
// x*W_ih at ~fp32 precision). Epilogue does pure nonlinearity + pred.
//   ext k0: x_hi*Wih_hi   k1: x_lo*Wih_hi   k2: x_hi*Wih_lo   k3: 1*bias

#define T 7
#define MTILE 64
#define NTH 512
#define WSTR 136
#define HSTR 136

#define W_OFF   0u
#define H0_OFF  139264u               // 512*136*2
#define H1_OFF  156672u
#define F32_OFF 174080u
#define F_WOUT 0                      // 128
#define F_XS   128                    // 64 rows x 8 slots
#define F_PRED 640                    // 2 x (64 rows x 8 col-warps)
#define F_COUNT 1664
#define SMEM_TOTAL (174080 + F_COUNT * 4)   // 180736

static __device__ __forceinline__ uint32_t smem_u32(const void* p) {
    uint32_t a;
    asm("{ .reg .u64 t; cvta.to.shared.u64 t, %1; cvt.u32.u64 %0, t; }"
        : "=r"(a) : "l"(p));
    return a;
}
static __device__ __forceinline__ float tanh_fast(float v) {
    float y; asm("tanh.approx.f32 %0, %1;" : "=f"(y) : "f"(v)); return y;
}
static __device__ __forceinline__ float sigmoid_fast(float v) {
    return 0.5f * tanh_fast(0.5f * v) + 0.5f;
}
static __device__ __forceinline__ uint32_t pack_bf16x2(float lo, float hi) {
    uint32_t r;
    asm("cvt.rn.bf16x2.f32 %0, %1, %2;" : "=r"(r) : "f"(hi), "f"(lo));
    return r;
}
static __device__ __forceinline__ float bf16_round(float v) {
    return __bfloat162float(__float2bfloat16_rn(v));
}

#define LDSM_X4(r0, r1, r2, r3, addr) \
    asm volatile("ldmatrix.sync.aligned.m8n8.x4.shared.b16 {%0,%1,%2,%3}, [%4];" \
        : "=r"(r0), "=r"(r1), "=r"(r2), "=r"(r3) : "r"(addr))

#define MMA16816(D, A, B0, B1) \
    asm volatile("mma.sync.aligned.m16n8k16.row.col.f32.bf16.bf16.f32 " \
        "{%0,%1,%2,%3}, {%4,%5,%6,%7}, {%8,%9}, {%0,%1,%2,%3};" \
        : "+f"((D)[0]), "+f"((D)[1]), "+f"((D)[2]), "+f"((D)[3]) \
        : "r"((A)[0]), "r"((A)[1]), "r"((A)[2]), "r"((A)[3]), "r"(B0), "r"(B1))

#define MMA16808(D, A0, A1, B0) \
    asm volatile("mma.sync.aligned.m16n8k8.row.col.f32.bf16.bf16.f32 " \
        "{%0,%1,%2,%3}, {%4,%5}, {%6}, {%0,%1,%2,%3};" \
        : "+f"((D)[0]), "+f"((D)[1]), "+f"((D)[2]), "+f"((D)[3]) \
        : "r"(A0), "r"(A1), "r"(B0))

__global__ __launch_bounds__(NTH, 1)
void lstm_mma_kernel(const float* __restrict__ x,
                     const float* __restrict__ x0,
                     const float* __restrict__ W_ih,
                     const float* __restrict__ W_hh,
                     const float* __restrict__ b_ih,
                     const float* __restrict__ b_hh,
                     const float* __restrict__ W_out,
                     const float* __restrict__ b_out,
                     float* __restrict__ out)
{
    extern __shared__ char smem[];
    const uint32_t sb = smem_u32(smem);
    float* f32s = (float*)(smem + F32_OFF);

    const int tid  = threadIdx.x;
    const int wid  = tid >> 5;
    const int grp  = wid >> 3;        // independent 32-row group
    const int gwid = wid & 7;         // col-warp: units gwid*16..+15
    const int lane = tid & 31;
    const int q    = lane & 3;
    const int par  = q & 1;
    const int hu   = q >> 1;
    const int rowBase = blockIdx.x * MTILE;

    // ---- one-time staging ----
#pragma unroll
    for (int it = 0; it < 32; it++) {
        int idx = tid + it * NTH;
        int j   = idx >> 5;
        int kq  = (idx & 31) * 4;
        int src = (j & 3) * 128 + (j >> 2);
        float4 w4 = *(const float4*)(W_hh + src * 128 + kq);
        uint32_t o = (uint32_t)(j * WSTR + kq) * 2;
        *(uint32_t*)(smem + o)     = pack_bf16x2(w4.x, w4.y);
        *(uint32_t*)(smem + o + 4) = pack_bf16x2(w4.z, w4.w);
    }
    for (int i = tid; i < (int)(64 * HSTR * 2 / 4); i += NTH)
        *(uint32_t*)(smem + H0_OFF + i * 4) = 0u;
    if (tid < 128) f32s[F_WOUT + tid] = W_out[tid];
    {   // 64 rows x 8 step slots
        int row = tid >> 3, sl = tid & 7;
        f32s[F_XS + tid] = (sl == 0) ? x0[rowBase + row]
                                     : x[(rowBase + row) * T + (sl > 6 ? 6 : sl - 1)];
    }

    // ---- B-ext fragments (loop-invariant, registers) ----
    // n-tile nt -> permuted col j; src W row = (j&3)*128 + (j>>2)
    uint32_t Bext[8];
#pragma unroll
    for (int nt = 0; nt < 8; nt++) {
        int j   = gwid * 64 + nt * 8 + (lane >> 2);
        int src = (j & 3) * 128 + (j >> 2);
        float wih  = W_ih[src];
        float bias = b_ih[src] + b_hh[src];
        float wih_hi = bf16_round(wih);
        float wih_lo = wih - wih_hi;
        Bext[nt] = (q == 0) ? pack_bf16x2(wih_hi, wih_hi)
                 : (q == 1) ? pack_bf16x2(wih_lo, bias)
                            : 0u;
    }

    __syncthreads();   // last CTA-wide barrier

    const float bout = b_out[0];

    float cst[2][8];
#pragma unroll
    for (int mi = 0; mi < 2; mi++)
#pragma unroll
        for (int nt = 0; nt < 8; nt++) cst[mi][nt] = 0.0f;

    const uint32_t aOff = (uint32_t)(((lane & 15) * HSTR + ((lane >> 4) & 1) * 8) * 2);
    const uint32_t bOff = (uint32_t)(((gwid * 64 + ((lane >> 4) & 1) * 8 + (lane & 7)) * WSTR
                                      + ((lane >> 3) & 1) * 8) * 2);
    const int rowIn = (lane >> 2) + par * 8;
    const int gtid  = tid & 255;
    const int barid = grp + 1;

    for (int s = 0; s < T; s++) {
        const uint32_t hcur = (s & 1) ? H1_OFF : H0_OFF;
        const uint32_t hnxt = (s & 1) ? H0_OFF : H1_OFF;

        float acc[2][8][4];
#pragma unroll
        for (int mi = 0; mi < 2; mi++)
#pragma unroll
            for (int nt = 0; nt < 8; nt++)
#pragma unroll
                for (int e = 0; e < 4; e++) acc[mi][nt][e] = 0.0f;

        // ---- ext chunk: x*W_ih + bias via m16n8k8, register A frags ----
#pragma unroll
        for (int mi = 0; mi < 2; mi++) {
            const int rb = grp * 32 + mi * 16 + (lane >> 2);
            float xa = f32s[F_XS + rb * 8 + s];
            float xb = f32s[F_XS + (rb + 8) * 8 + s];
            float xa_hi = bf16_round(xa), xa_lo = xa - xa_hi;
            float xb_hi = bf16_round(xb), xb_lo = xb - xb_hi;
            uint32_t a0 = (q == 0) ? pack_bf16x2(xa_hi, xa_lo)
                        : (q == 1) ? pack_bf16x2(xa_hi, 1.0f) : 0u;
            uint32_t a1 = (q == 0) ? pack_bf16x2(xb_hi, xb_lo)
                        : (q == 1) ? pack_bf16x2(xb_hi, 1.0f) : 0u;
#pragma unroll
            for (int nt = 0; nt < 8; nt++)
                MMA16808(acc[mi][nt], a0, a1, Bext[nt]);
        }

        // ---- main K=128 ----
#pragma unroll
        for (int kc = 0; kc < 8; kc++) {
            uint32_t a[2][4];
#pragma unroll
            for (int mi = 0; mi < 2; mi++)
                LDSM_X4(a[mi][0], a[mi][1], a[mi][2], a[mi][3],
                        sb + hcur + aOff +
                        (uint32_t)(((grp * 32 + mi * 16) * HSTR + kc * 16) * 2));
#pragma unroll
            for (int np = 0; np < 4; np++) {
                uint32_t b0, b1, b2, b3;
                LDSM_X4(b0, b1, b2, b3,
                        sb + W_OFF + bOff + (uint32_t)((np * 16 * WSTR + kc * 16) * 2));
#pragma unroll
                for (int mi = 0; mi < 2; mi++) {
                    MMA16816(acc[mi][np * 2],     a[mi], b0, b1);
                    MMA16816(acc[mi][np * 2 + 1], a[mi], b2, b3);
                }
            }
        }

        // ---- epilogue: pure nonlinearity + state + pred ----
        const int pb = F_PRED + (s & 1) * 512;
#pragma unroll
        for (int mi = 0; mi < 2; mi++) {
            const int row_eff = grp * 32 + mi * 16 + rowIn;
            float pred = 0.0f;
#pragma unroll
            for (int nt = 0; nt < 8; nt++) {
                float s0 = par ? acc[mi][nt][0] : acc[mi][nt][2];
                float s1 = par ? acc[mi][nt][1] : acc[mi][nt][3];
                float r0 = __shfl_xor_sync(0xffffffffu, s0, 1);
                float r1 = __shfl_xor_sync(0xffffffffu, s1, 1);
                float gi = par ? r0 : acc[mi][nt][0];
                float gf = par ? r1 : acc[mi][nt][1];
                float gg = par ? acc[mi][nt][2] : r0;
                float go = par ? acc[mi][nt][3] : r1;

                const int u = gwid * 16 + nt * 2 + hu;
                float ig = sigmoid_fast(gi);
                float fg = sigmoid_fast(gf);
                float g_ = tanh_fast(gg);
                float og = sigmoid_fast(go);
                float cn = fg * cst[mi][nt] + ig * g_;
                cst[mi][nt] = cn;
                float hn = og * tanh_fast(cn);
                pred += hn * f32s[F_WOUT + u];

                *(__nv_bfloat16*)(smem + hnxt + (uint32_t)((row_eff * HSTR + u) * 2)) =
                    __float2bfloat16(hn);
            }
            pred += __shfl_xor_sync(0xffffffffu, pred, 2);
            if (q < 2) f32s[pb + row_eff * 8 + gwid] = pred;
        }

        asm volatile("bar.sync %0, %1;" :: "r"(barid), "r"(256) : "memory");

        if (gtid < 32) {
            const int row = grp * 32 + gtid;
            float p = bout;
            const float* pp = &f32s[pb + row * 8];
#pragma unroll
            for (int w = 0; w < 8; w++) p += pp[w];
            out[(rowBase + row) * T + s] = p;
        }
    }
}

extern "C" void kernel_launch(void* const* d_in, const int* in_sizes, int n_in,
                              void* d_out, int out_size)
{
    const float* x     = (const float*)d_in[0];
    const float* x0    = (const float*)d_in[1];
    const float* W_ih  = (const float*)d_in[2];
    const float* W_hh  = (const float*)d_in[3];
    const float* b_ih  = (const float*)d_in[4];
    const float* b_hh  = (const float*)d_in[5];
    const float* W_out = (const float*)d_in[6];
    const float* b_out = (const float*)d_in[7];
    float* out = (float*)d_out;

    const int B = in_sizes[1];

    cudaFuncSetAttribute(lstm_mma_kernel,
                         cudaFuncAttributeMaxDynamicSharedMemorySize, SMEM_TOTAL);

    lstm_mma_kernel<<<B / MTILE, NTH, SMEM_TOTAL>>>(
        x, x0, W_ih, W_hh, b_ih, b_hh, W_out, b_out, out);
}

// round 8
// speedup vs baseline: 1.0600x; 1.0600x over previous
#include <cuda_runtime.h>
#include <cuda_bf16.h>
#include <cstdint>

// LSTM B=65536, T=7, H=128, fused recurrence via warp-level mma.sync (bf16->f32).
// CTA = 512 thr / 16 warps / 64 rows, TWO independent 8-warp groups (named bars).
// R8: per-step phase fusion. MMA split into two np-passes; the second pass
// interleaves one completed cell's epilogue per kc chunk, so MUFU-throttled
// epilogue work coexists with tensor/ldsm work in the same warp stream.
// Numerics identical to R6 (bias + x*W_ih in fp32 epilogue).

#define T 7
#define MTILE 64
#define NTH 512
#define WSTR 136   // bf16 elems per W' row (17x16B pitch -> conflict-free ldmatrix)
#define HSTR 136

#define W_OFF   0u
#define H0_OFF  139264u               // 512*136*2
#define H1_OFF  156672u
#define F32_OFF 174080u
#define F_BIAS 0
#define F_WIH  512
#define F_WOUT 1024
#define F_XS   1152                   // 64 rows x 8 slots
#define F_PRED 1664                   // 2 x (64 rows x 8 col-warps)
#define F_COUNT 2688
#define SMEM_TOTAL (174080 + F_COUNT * 4)   // 184832

static __device__ __forceinline__ uint32_t smem_u32(const void* p) {
    uint32_t a;
    asm("{ .reg .u64 t; cvta.to.shared.u64 t, %1; cvt.u32.u64 %0, t; }"
        : "=r"(a) : "l"(p));
    return a;
}
static __device__ __forceinline__ float tanh_fast(float v) {
    float y; asm("tanh.approx.f32 %0, %1;" : "=f"(y) : "f"(v)); return y;
}
static __device__ __forceinline__ float sigmoid_fast(float v) {
    return 0.5f * tanh_fast(0.5f * v) + 0.5f;
}
static __device__ __forceinline__ uint32_t pack_bf16x2(float lo, float hi) {
    uint32_t r;
    asm("cvt.rn.bf16x2.f32 %0, %1, %2;" : "=r"(r) : "f"(hi), "f"(lo));
    return r;
}

#define LDSM_X4(r0, r1, r2, r3, addr) \
    asm volatile("ldmatrix.sync.aligned.m8n8.x4.shared.b16 {%0,%1,%2,%3}, [%4];" \
        : "=r"(r0), "=r"(r1), "=r"(r2), "=r"(r3) : "r"(addr))

#define MMA16816(D, A, B0, B1) \
    asm volatile("mma.sync.aligned.m16n8k16.row.col.f32.bf16.bf16.f32 " \
        "{%0,%1,%2,%3}, {%4,%5,%6,%7}, {%8,%9}, {%0,%1,%2,%3};" \
        : "+f"((D)[0]), "+f"((D)[1]), "+f"((D)[2]), "+f"((D)[3]) \
        : "r"((A)[0]), "r"((A)[1]), "r"((A)[2]), "r"((A)[3]), "r"(B0), "r"(B1))

__global__ __launch_bounds__(NTH, 1)
void lstm_mma_kernel(const float* __restrict__ x,
                     const float* __restrict__ x0,
                     const float* __restrict__ W_ih,
                     const float* __restrict__ W_hh,
                     const float* __restrict__ b_ih,
                     const float* __restrict__ b_hh,
                     const float* __restrict__ W_out,
                     const float* __restrict__ b_out,
                     float* __restrict__ out)
{
    extern __shared__ char smem[];
    const uint32_t sb = smem_u32(smem);
    float* f32s = (float*)(smem + F32_OFF);

    const int tid  = threadIdx.x;
    const int wid  = tid >> 5;
    const int grp  = wid >> 3;        // independent 32-row group
    const int gwid = wid & 7;         // col-warp: units gwid*16..+15
    const int lane = tid & 31;
    const int q    = lane & 3;
    const int par  = q & 1;
    const int hu   = q >> 1;
    const int rowBase = blockIdx.x * MTILE;

    // ---- one-time staging (full CTA) ----
#pragma unroll
    for (int it = 0; it < 32; it++) {
        int idx = tid + it * NTH;
        int j   = idx >> 5;
        int kq  = (idx & 31) * 4;
        int src = (j & 3) * 128 + (j >> 2);
        float4 w4 = *(const float4*)(W_hh + src * 128 + kq);
        uint32_t o = (uint32_t)(j * WSTR + kq) * 2;
        *(uint32_t*)(smem + o)     = pack_bf16x2(w4.x, w4.y);
        *(uint32_t*)(smem + o + 4) = pack_bf16x2(w4.z, w4.w);
    }
    for (int i = tid; i < (int)(64 * HSTR * 2 / 4); i += NTH)
        *(uint32_t*)(smem + H0_OFF + i * 4) = 0u;
    for (int j = tid; j < 512; j += NTH) {
        int u = j >> 2, g = j & 3, src = g * 128 + u;
        f32s[F_BIAS + j] = b_ih[src] + b_hh[src];
        f32s[F_WIH + j]  = W_ih[src];
    }
    if (tid < 128) f32s[F_WOUT + tid] = W_out[tid];
    {   // 64 rows x 8 step slots
        int row = tid >> 3, sl = tid & 7;
        f32s[F_XS + tid] = (sl == 0) ? x0[rowBase + row]
                                     : x[(rowBase + row) * T + (sl > 6 ? 6 : sl - 1)];
    }
    __syncthreads();   // last CTA-wide barrier; groups free-run from here

    const float bout = b_out[0];

    float cst[2][8];
#pragma unroll
    for (int mi = 0; mi < 2; mi++)
#pragma unroll
        for (int nt = 0; nt < 8; nt++) cst[mi][nt] = 0.0f;

    const uint32_t aOff = (uint32_t)(((lane & 15) * HSTR + ((lane >> 4) & 1) * 8) * 2);
    const uint32_t bOff = (uint32_t)(((gwid * 64 + ((lane >> 4) & 1) * 8 + (lane & 7)) * WSTR
                                      + ((lane >> 3) & 1) * 8) * 2);
    const int rowIn = (lane >> 2) + par * 8;
    const int gtid  = tid & 255;
    const int barid = grp + 1;

    for (int s = 0; s < T; s++) {
        const uint32_t hcur = (s & 1) ? H1_OFF : H0_OFF;
        const uint32_t hnxt = (s & 1) ? H0_OFF : H1_OFF;

        float acc[2][8][4];
#pragma unroll
        for (int mi = 0; mi < 2; mi++)
#pragma unroll
            for (int nt = 0; nt < 8; nt++)
#pragma unroll
                for (int e = 0; e < 4; e++) acc[mi][nt][e] = 0.0f;

        const float xv[2] = { f32s[F_XS + (grp * 32 + rowIn) * 8 + s],
                              f32s[F_XS + (grp * 32 + 16 + rowIn) * 8 + s] };
        float pred[2] = {0.0f, 0.0f};

        // one completed cell's full epilogue (gate regroup -> state -> h/pred)
        auto epi_cell = [&](int mi, int nt) {
            float s0 = par ? acc[mi][nt][0] : acc[mi][nt][2];
            float s1 = par ? acc[mi][nt][1] : acc[mi][nt][3];
            float r0 = __shfl_xor_sync(0xffffffffu, s0, 1);
            float r1 = __shfl_xor_sync(0xffffffffu, s1, 1);
            float gi = par ? r0 : acc[mi][nt][0];
            float gf = par ? r1 : acc[mi][nt][1];
            float gg = par ? acc[mi][nt][2] : r0;
            float go = par ? acc[mi][nt][3] : r1;

            const int u = gwid * 16 + nt * 2 + hu;
            const float4 b4 = *(const float4*)&f32s[F_BIAS + u * 4];
            const float4 w4 = *(const float4*)&f32s[F_WIH + u * 4];
            gi += b4.x + xv[mi] * w4.x;
            gf += b4.y + xv[mi] * w4.y;
            gg += b4.z + xv[mi] * w4.z;
            go += b4.w + xv[mi] * w4.w;

            float ig = sigmoid_fast(gi);
            float fg = sigmoid_fast(gf);
            float g_ = tanh_fast(gg);
            float og = sigmoid_fast(go);
            float cn = fg * cst[mi][nt] + ig * g_;
            cst[mi][nt] = cn;
            float hn = og * tanh_fast(cn);
            pred[mi] += hn * f32s[F_WOUT + u];

            const int row_eff = grp * 32 + mi * 16 + rowIn;
            *(__nv_bfloat16*)(smem + hnxt + (uint32_t)((row_eff * HSTR + u) * 2)) =
                __float2bfloat16(hn);
        };

        // ---- PASS 1: np 0..1 -> cells nt 0..3 complete ----
#pragma unroll
        for (int kc = 0; kc < 8; kc++) {
            uint32_t a[2][4];
#pragma unroll
            for (int mi = 0; mi < 2; mi++)
                LDSM_X4(a[mi][0], a[mi][1], a[mi][2], a[mi][3],
                        sb + hcur + aOff +
                        (uint32_t)(((grp * 32 + mi * 16) * HSTR + kc * 16) * 2));
#pragma unroll
            for (int np = 0; np < 2; np++) {
                uint32_t b0, b1, b2, b3;
                LDSM_X4(b0, b1, b2, b3,
                        sb + W_OFF + bOff + (uint32_t)((np * 16 * WSTR + kc * 16) * 2));
#pragma unroll
                for (int mi = 0; mi < 2; mi++) {
                    MMA16816(acc[mi][np * 2],     a[mi], b0, b1);
                    MMA16816(acc[mi][np * 2 + 1], a[mi], b2, b3);
                }
            }
        }

        // ---- FUSED PASS 2 (np 2..3) + epilogue of pass-1 cells ----
#pragma unroll
        for (int kc = 0; kc < 8; kc++) {
            uint32_t a[2][4];
#pragma unroll
            for (int mi = 0; mi < 2; mi++)
                LDSM_X4(a[mi][0], a[mi][1], a[mi][2], a[mi][3],
                        sb + hcur + aOff +
                        (uint32_t)(((grp * 32 + mi * 16) * HSTR + kc * 16) * 2));
#pragma unroll
            for (int np = 2; np < 4; np++) {
                uint32_t b0, b1, b2, b3;
                LDSM_X4(b0, b1, b2, b3,
                        sb + W_OFF + bOff + (uint32_t)((np * 16 * WSTR + kc * 16) * 2));
#pragma unroll
                for (int mi = 0; mi < 2; mi++) {
                    MMA16816(acc[mi][np * 2],     a[mi], b0, b1);
                    MMA16816(acc[mi][np * 2 + 1], a[mi], b2, b3);
                }
            }
            epi_cell(kc & 1, kc >> 1);    // one pass-1 cell per chunk
        }

        // ---- trailing epilogue: cells nt 4..7 ----
#pragma unroll
        for (int c = 0; c < 8; c++)
            epi_cell(c & 1, 4 + (c >> 1));

        const int pb = F_PRED + (s & 1) * 512;
#pragma unroll
        for (int mi = 0; mi < 2; mi++) {
            pred[mi] += __shfl_xor_sync(0xffffffffu, pred[mi], 2);
            if (q < 2)
                f32s[pb + (grp * 32 + mi * 16 + rowIn) * 8 + gwid] = pred[mi];
        }

        asm volatile("bar.sync %0, %1;" :: "r"(barid), "r"(256) : "memory");

        if (gtid < 32) {
            const int row = grp * 32 + gtid;
            float p = bout;
            const float* pp = &f32s[pb + row * 8];
#pragma unroll
            for (int w = 0; w < 8; w++) p += pp[w];
            out[(rowBase + row) * T + s] = p;
        }
    }
}

extern "C" void kernel_launch(void* const* d_in, const int* in_sizes, int n_in,
                              void* d_out, int out_size)
{
    const float* x     = (const float*)d_in[0];
    const float* x0    = (const float*)d_in[1];
    const float* W_ih  = (const float*)d_in[2];
    const float* W_hh  = (const float*)d_in[3];
    const float* b_ih  = (const float*)d_in[4];
    const float* b_hh  = (const float*)d_in[5];
    const float* W_out = (const float*)d_in[6];
    const float* b_out = (const float*)d_in[7];
    float* out = (float*)d_out;

    const int B = in_sizes[1];

    cudaFuncSetAttribute(lstm_mma_kernel,
                         cudaFuncAttributeMaxDynamicSharedMemorySize, SMEM_TOTAL);

    lstm_mma_kernel<<<B / MTILE, NTH, SMEM_TOTAL>>>(
        x, x0, W_ih, W_hh, b_ih, b_hh, W_out, b_out, out);
}